// round 8
// baseline (speedup 1.0000x reference)
#include <cuda_runtime.h>
#include <cuda_fp16.h>
#include <cstdint>

// Problem constants
#define B_DIM   512
#define QB      128             // batch rows per quarter
#define IN_DIM  65536
#define OUT_DIM 16384
#define K_DIM   32
#define OTILE   8
#define GBLK    (OUT_DIM / OTILE)   // 2048 gather blocks per quarter
#define TBLK    2048                // transpose tiles per quarter

// 64 MB scratch for transposed x in fp16: xt[in][b]
__device__ __half g_xt_h[(size_t)IN_DIM * B_DIM];

// Bit-reinterpretation helpers
__device__ __forceinline__ unsigned int h2_to_u32(__half2 h) {
    union { __half2 h; unsigned int u; } c; c.h = h; return c.u;
}
__device__ __forceinline__ float2 u32_to_f2(unsigned int u) {
    union { unsigned int u; __half2 h; } c; c.u = u;
    return __half22float2(c.h);
}

// Shared-memory shapes (union -> fused kernel footprint = max, not sum)
struct SmemT {
    float4 tile4[32][33];                      // 16.9 KB
};
struct SmemG {
    int4   sidx4[OTILE][K_DIM / 4];
    float4 sw4[OTILE][K_DIM / 4];
    float  sbias[OTILE];
    float  sout[OTILE][QB + 8];                // [o][b-local]
};
union SmemU { SmemT t; SmemG g; };

// ---------------------------------------------------------------------------
// Transpose tile body: 32 b-rows x 128 in-cols of x -> fp16 xt.
// ---------------------------------------------------------------------------
__device__ __forceinline__ void transpose_tile(
    const float* __restrict__ x, int in0, int b0, SmemT& s)
{
    const int t = threadIdx.x;

    const int c4 = t & 31;
    const int r0 = t >> 5;
    #pragma unroll
    for (int it = 0; it < 4; it++) {
        const int r = r0 + 8 * it;
        s.tile4[r][c4] =
            *(const float4*)&x[(size_t)(b0 + r) * IN_DIM + in0 + 4 * c4];
    }
    __syncthreads();

    const int i = t >> 1;                      // in-row 0..127
    const int p = t & 1;                       // b-chunk (16 b = 32B)
    const int c  = i >> 2;
    const int cc = i & 3;

    __half2 h2[8];
    #pragma unroll
    for (int j = 0; j < 8; j++) {
        const float f0 = ((const float*)&s.tile4[16 * p + 2 * j + 0][c])[cc];
        const float f1 = ((const float*)&s.tile4[16 * p + 2 * j + 1][c])[cc];
        h2[j] = __floats2half2_rn(f0, f1);
    }
    uint4 u0, u1;
    u0.x = h2_to_u32(h2[0]); u0.y = h2_to_u32(h2[1]);
    u0.z = h2_to_u32(h2[2]); u0.w = h2_to_u32(h2[3]);
    u1.x = h2_to_u32(h2[4]); u1.y = h2_to_u32(h2[5]);
    u1.z = h2_to_u32(h2[6]); u1.w = h2_to_u32(h2[7]);

    uint4* dst = (uint4*)&g_xt_h[(size_t)(in0 + i) * B_DIM + b0 + 16 * p];
    dst[0] = u0;
    dst[1] = u1;
}

// ---------------------------------------------------------------------------
// Gather block body: 8 outputs x one b-quarter. Warp per output; lane owns
// 4 b-rows via one LDG.64 per (o,k) -> 256B contiguous column reads.
// ---------------------------------------------------------------------------
__device__ __forceinline__ void gather_block(
    const int*   __restrict__ idx,
    const float* __restrict__ w,
    const float* __restrict__ bias,
    float*       __restrict__ out,
    int q, int o0, SmemG& s)
{
    const int tid = threadIdx.x;
    const int wo  = tid >> 5;
    const int l   = tid & 31;

    if (tid < 64) {
        s.sidx4[tid >> 3][tid & 7] =
            ((const int4*)idx)[(size_t)(o0 + (tid >> 3)) * 8 + (tid & 7)];
    } else if (tid < 128) {
        const int u = tid - 64;
        s.sw4[u >> 3][u & 7] =
            ((const float4*)w)[(size_t)(o0 + (u >> 3)) * 8 + (u & 7)];
    } else if (tid < 128 + OTILE) {
        s.sbias[tid - 128] = bias[o0 + (tid - 128)];
    }
    __syncthreads();

    // xt row = 512 halves = 128 uint2 slots; quarter q = slots [32q, 32q+32).
    const uint2* __restrict__ xt8 =
        reinterpret_cast<const uint2*>(g_xt_h) + (size_t)q * 32 + l;

    float a0 = 0.f, a1 = 0.f, a2 = 0.f, a3 = 0.f;

    #pragma unroll
    for (int k4 = 0; k4 < K_DIM / 4; k4++) {
        const int4   ii = s.sidx4[wo][k4];
        const float4 ww = s.sw4[wo][k4];
        const uint2 v0 = __ldg(&xt8[(size_t)ii.x * 128]);
        const uint2 v1 = __ldg(&xt8[(size_t)ii.y * 128]);
        const uint2 v2 = __ldg(&xt8[(size_t)ii.z * 128]);
        const uint2 v3 = __ldg(&xt8[(size_t)ii.w * 128]);

        {
            const float2 f0 = u32_to_f2(v0.x), f1 = u32_to_f2(v0.y);
            a0 += f0.x * ww.x; a1 += f0.y * ww.x;
            a2 += f1.x * ww.x; a3 += f1.y * ww.x;
        }
        {
            const float2 f0 = u32_to_f2(v1.x), f1 = u32_to_f2(v1.y);
            a0 += f0.x * ww.y; a1 += f0.y * ww.y;
            a2 += f1.x * ww.y; a3 += f1.y * ww.y;
        }
        {
            const float2 f0 = u32_to_f2(v2.x), f1 = u32_to_f2(v2.y);
            a0 += f0.x * ww.z; a1 += f0.y * ww.z;
            a2 += f1.x * ww.z; a3 += f1.y * ww.z;
        }
        {
            const float2 f0 = u32_to_f2(v3.x), f1 = u32_to_f2(v3.y);
            a0 += f0.x * ww.w; a1 += f0.y * ww.w;
            a2 += f1.x * ww.w; a3 += f1.y * ww.w;
        }
    }

    const float bv = s.sbias[wo];
    float4 sv = make_float4(a0 + bv, a1 + bv, a2 + bv, a3 + bv);
    *(float4*)&s.sout[wo][4 * l] = sv;       // warp: 512B contiguous STS
    __syncthreads();

    // Coalesced out store: threads 0..127 own b = q*128 + tid.
    if (tid < QB) {
        const int b = q * QB + tid;
        float4 r0, r1;
        r0.x = s.sout[0][tid]; r0.y = s.sout[1][tid];
        r0.z = s.sout[2][tid]; r0.w = s.sout[3][tid];
        r1.x = s.sout[4][tid]; r1.y = s.sout[5][tid];
        r1.z = s.sout[6][tid]; r1.w = s.sout[7][tid];
        float4* dst = reinterpret_cast<float4*>(out + (size_t)b * OUT_DIM + o0);
        dst[0] = r0;
        dst[1] = r1;
    }
}

// ---------------------------------------------------------------------------
// Kernels
// ---------------------------------------------------------------------------
__global__ __launch_bounds__(256) void transpose_q_kernel(
    const float* __restrict__ x, int q)
{
    __shared__ SmemT s;
    const int j   = blockIdx.x;                // 0..2047
    const int in0 = (j & 511) << 7;
    const int b0  = q * QB + (j >> 9) * 32;
    transpose_tile(x, in0, b0, s);
}

__global__ __launch_bounds__(256) void gather_q_kernel(
    const int*   __restrict__ idx,
    const float* __restrict__ w,
    const float* __restrict__ bias,
    float*       __restrict__ out,
    int q)
{
    __shared__ SmemG s;
    gather_block(idx, w, bias, out, q, blockIdx.x * OTILE, s);
}

// Fused: gather(quarter q) and transpose(quarter q+1) are independent
// (disjoint xt regions) -> one launch, partitioned by blockIdx. Gather blocks
// first (critical path).
__global__ __launch_bounds__(256) void fused_gq_tq1_kernel(
    const float* __restrict__ x,
    const int*   __restrict__ idx,
    const float* __restrict__ w,
    const float* __restrict__ bias,
    float*       __restrict__ out,
    int q)
{
    __shared__ SmemU sm;
    const int bx = blockIdx.x;
    if (bx < GBLK) {
        gather_block(idx, w, bias, out, q, bx * OTILE, sm.g);
    } else {
        const int j   = bx - GBLK;             // 0..2047
        const int in0 = (j & 511) << 7;
        const int b0  = (q + 1) * QB + (j >> 9) * 32;
        transpose_tile(x, in0, b0, sm.t);
    }
}

// ---------------------------------------------------------------------------
// Launch: T(q0) ; [G(q0)||T(q1)] ; [G(q1)||T(q2)] ; [G(q2)||T(q3)] ; G(q3)
// Stream-order dependencies provide all synchronization.
// ---------------------------------------------------------------------------
extern "C" void kernel_launch(void* const* d_in, const int* in_sizes, int n_in,
                              void* d_out, int out_size) {
    const float* x    = (const float*)d_in[0];
    const int*   idx  = (const int*)  d_in[1];
    const float* w    = (const float*)d_in[2];
    const float* bias = (const float*)d_in[3];
    float*       out  = (float*)d_out;

    transpose_q_kernel<<<TBLK, 256>>>(x, 0);
    fused_gq_tq1_kernel<<<GBLK + TBLK, 256>>>(x, idx, w, bias, out, 0);
    fused_gq_tq1_kernel<<<GBLK + TBLK, 256>>>(x, idx, w, bias, out, 1);
    fused_gq_tq1_kernel<<<GBLK + TBLK, 256>>>(x, idx, w, bias, out, 2);
    gather_q_kernel<<<GBLK, 256>>>(idx, w, bias, out, 3);
}

// round 9
// speedup vs baseline: 1.0493x; 1.0493x over previous
#include <cuda_runtime.h>
#include <cuda_fp16.h>
#include <cstdint>

// Problem constants
#define B_DIM   512
#define HALF_B  256
#define IN_DIM  65536
#define OUT_DIM 16384
#define K_DIM   32
#define OTILE   8

#define TBLK_H  4096            // transpose tiles per half
#define GBLK_H  2048            // gather blocks per half
#define GRID_TOTAL (2 * TBLK_H + 2 * GBLK_H)   // 12288

// 64 MB scratch for transposed x in fp16: xt[in][b]
__device__ __half g_xt_h[(size_t)IN_DIM * B_DIM];

// Completion counters (reset each call)
__device__ int g_tdone[2];

__global__ void reset_kernel() { g_tdone[0] = 0; g_tdone[1] = 0; }

// Bit-reinterpretation helpers
__device__ __forceinline__ unsigned int h2_to_u32(__half2 h) {
    union { __half2 h; unsigned int u; } c; c.h = h; return c.u;
}
__device__ __forceinline__ float2 u32_to_f2(unsigned int u) {
    union { unsigned int u; __half2 h; } c; c.u = u;
    return __half22float2(c.h);
}

// Shared-memory shapes (union -> fused footprint = max, not sum)
struct SmemT {
    float4 tile4[32][33];                      // 16.9 KB
};
struct SmemG {
    int4   sidx4[OTILE][K_DIM / 4];
    float4 sw4[OTILE][K_DIM / 4];
    float  sbias[OTILE];
    float  sout[OTILE][HALF_B + 8];
};
union SmemU { SmemT t; SmemG g; };

// ---------------------------------------------------------------------------
// Transpose tile body: 32 b-rows x 128 in-cols of x -> fp16 xt. On完成,
// arrives on g_tdone[half].
// ---------------------------------------------------------------------------
__device__ __forceinline__ void transpose_tile(
    const float* __restrict__ x, int in0, int b0, int half, SmemT& s)
{
    const int t = threadIdx.x;

    const int c4 = t & 31;
    const int r0 = t >> 5;
    #pragma unroll
    for (int it = 0; it < 4; it++) {
        const int r = r0 + 8 * it;
        s.tile4[r][c4] =
            *(const float4*)&x[(size_t)(b0 + r) * IN_DIM + in0 + 4 * c4];
    }
    __syncthreads();

    const int i = t >> 1;                      // in-row 0..127
    const int p = t & 1;                       // b-chunk (16 b = 32B)
    const int c  = i >> 2;
    const int cc = i & 3;

    __half2 h2[8];
    #pragma unroll
    for (int j = 0; j < 8; j++) {
        const float f0 = ((const float*)&s.tile4[16 * p + 2 * j + 0][c])[cc];
        const float f1 = ((const float*)&s.tile4[16 * p + 2 * j + 1][c])[cc];
        h2[j] = __floats2half2_rn(f0, f1);
    }
    uint4 u0, u1;
    u0.x = h2_to_u32(h2[0]); u0.y = h2_to_u32(h2[1]);
    u0.z = h2_to_u32(h2[2]); u0.w = h2_to_u32(h2[3]);
    u1.x = h2_to_u32(h2[4]); u1.y = h2_to_u32(h2[5]);
    u1.z = h2_to_u32(h2[6]); u1.w = h2_to_u32(h2[7]);

    uint4* dst = (uint4*)&g_xt_h[(size_t)(in0 + i) * B_DIM + b0 + 16 * p];
    dst[0] = u0;
    dst[1] = u1;

    // Release: all gmem stores above, then arrive.
    __syncthreads();
    if (t == 0) {
        __threadfence();
        atomicAdd(&g_tdone[half], 1);
    }
}

// ---------------------------------------------------------------------------
// Gather block body: 8 outputs x one b-half. Warp per output; lane owns
// 8 b-rows via one LDG.128 per (o,k) -> 512B contiguous column reads.
// Gates on g_tdone[half] (acquire) before touching xt.
// ---------------------------------------------------------------------------
__device__ __forceinline__ void gather_block(
    const int*   __restrict__ idx,
    const float* __restrict__ w,
    const float* __restrict__ bias,
    float*       __restrict__ out,
    int half, int o0, SmemG& s)
{
    const int tid = threadIdx.x;
    const int wo  = tid >> 5;
    const int l   = tid & 31;

    // Stage idx/w/bias first (overlaps with the wait below)
    if (tid < 64) {
        s.sidx4[tid >> 3][tid & 7] =
            ((const int4*)idx)[(size_t)(o0 + (tid >> 3)) * 8 + (tid & 7)];
    } else if (tid < 128) {
        const int u = tid - 64;
        s.sw4[u >> 3][u & 7] =
            ((const float4*)w)[(size_t)(o0 + (u >> 3)) * 8 + (u & 7)];
    } else if (tid < 128 + OTILE) {
        s.sbias[tid - 128] = bias[o0 + (tid - 128)];
    }

    // Acquire: wait until this half's transpose fully arrived.
    if (tid == 0) {
        while (*(volatile int*)&g_tdone[half] < TBLK_H) __nanosleep(64);
        __threadfence();
    }
    __syncthreads();

    const uint4* __restrict__ xt16 =
        reinterpret_cast<const uint4*>(g_xt_h) + (size_t)half * 32 + l;

    float a0 = 0.f, a1 = 0.f, a2 = 0.f, a3 = 0.f;
    float a4 = 0.f, a5 = 0.f, a6 = 0.f, a7 = 0.f;

    #pragma unroll
    for (int k4 = 0; k4 < K_DIM / 4; k4++) {
        const int4   ii = s.sidx4[wo][k4];
        const float4 ww = s.sw4[wo][k4];
        const uint4 v0 = __ldg(&xt16[(size_t)ii.x * 64]);
        const uint4 v1 = __ldg(&xt16[(size_t)ii.y * 64]);
        const uint4 v2 = __ldg(&xt16[(size_t)ii.z * 64]);
        const uint4 v3 = __ldg(&xt16[(size_t)ii.w * 64]);

        {
            const float2 f0 = u32_to_f2(v0.x), f1 = u32_to_f2(v0.y);
            const float2 f2 = u32_to_f2(v0.z), f3 = u32_to_f2(v0.w);
            a0 += f0.x * ww.x; a1 += f0.y * ww.x;
            a2 += f1.x * ww.x; a3 += f1.y * ww.x;
            a4 += f2.x * ww.x; a5 += f2.y * ww.x;
            a6 += f3.x * ww.x; a7 += f3.y * ww.x;
        }
        {
            const float2 f0 = u32_to_f2(v1.x), f1 = u32_to_f2(v1.y);
            const float2 f2 = u32_to_f2(v1.z), f3 = u32_to_f2(v1.w);
            a0 += f0.x * ww.y; a1 += f0.y * ww.y;
            a2 += f1.x * ww.y; a3 += f1.y * ww.y;
            a4 += f2.x * ww.y; a5 += f2.y * ww.y;
            a6 += f3.x * ww.y; a7 += f3.y * ww.y;
        }
        {
            const float2 f0 = u32_to_f2(v2.x), f1 = u32_to_f2(v2.y);
            const float2 f2 = u32_to_f2(v2.z), f3 = u32_to_f2(v2.w);
            a0 += f0.x * ww.z; a1 += f0.y * ww.z;
            a2 += f1.x * ww.z; a3 += f1.y * ww.z;
            a4 += f2.x * ww.z; a5 += f2.y * ww.z;
            a6 += f3.x * ww.z; a7 += f3.y * ww.z;
        }
        {
            const float2 f0 = u32_to_f2(v3.x), f1 = u32_to_f2(v3.y);
            const float2 f2 = u32_to_f2(v3.z), f3 = u32_to_f2(v3.w);
            a0 += f0.x * ww.w; a1 += f0.y * ww.w;
            a2 += f1.x * ww.w; a3 += f1.y * ww.w;
            a4 += f2.x * ww.w; a5 += f2.y * ww.w;
            a6 += f3.x * ww.w; a7 += f3.y * ww.w;
        }
    }

    const float bv = s.sbias[wo];
    float4 s0 = make_float4(a0 + bv, a1 + bv, a2 + bv, a3 + bv);
    float4 s1 = make_float4(a4 + bv, a5 + bv, a6 + bv, a7 + bv);
    *(float4*)&s.sout[wo][8 * l + 0] = s0;
    *(float4*)&s.sout[wo][8 * l + 4] = s1;
    __syncthreads();

    {
        const int b = half * HALF_B + tid;
        float4 r0, r1;
        r0.x = s.sout[0][tid]; r0.y = s.sout[1][tid];
        r0.z = s.sout[2][tid]; r0.w = s.sout[3][tid];
        r1.x = s.sout[4][tid]; r1.y = s.sout[5][tid];
        r1.z = s.sout[6][tid]; r1.w = s.sout[7][tid];
        float4* dst = reinterpret_cast<float4*>(out + (size_t)b * OUT_DIM + o0);
        dst[0] = r0;
        dst[1] = r1;
    }
}

// ---------------------------------------------------------------------------
// Single mega-kernel. Static blockIdx partition replicates the R7 pipeline
// without launch boundaries:
//   [0,4096):        T(h0)
//   [4096,10240):    interleaved 2:1  T(h1) : G(h0)
//   [10240,12288):   G(h1)
// Safety: CTAs are claimed in bid order, so every T(h) block is claimed (and
// thus runs to completion) before any G(h) block can be resident -> the
// counters always reach TBLK_H; spins terminate.
// ---------------------------------------------------------------------------
__global__ __launch_bounds__(256) void mega_kernel(
    const float* __restrict__ x,
    const int*   __restrict__ idx,
    const float* __restrict__ w,
    const float* __restrict__ bias,
    float*       __restrict__ out)
{
    __shared__ SmemU sm;
    const int bx = blockIdx.x;

    if (bx < TBLK_H) {
        // T(h0)
        const int j = bx;
        transpose_tile(x, (j & 511) << 7, (j >> 9) * 32, 0, sm.t);
    } else if (bx < TBLK_H + TBLK_H + GBLK_H) {
        const int r   = bx - TBLK_H;           // 0..6143
        const int grp = r / 3;                 // 0..2047
        const int rem = r - 3 * grp;
        if (rem < 2) {
            // T(h1)
            const int j = 2 * grp + rem;       // 0..4095
            transpose_tile(x, (j & 511) << 7, HALF_B + (j >> 9) * 32, 1, sm.t);
        } else {
            // G(h0)
            gather_block(idx, w, bias, out, 0, grp * OTILE, sm.g);
        }
    } else {
        // G(h1)
        const int j = bx - (TBLK_H + TBLK_H + GBLK_H);
        gather_block(idx, w, bias, out, 1, j * OTILE, sm.g);
    }
}

// ---------------------------------------------------------------------------
// Launch
// ---------------------------------------------------------------------------
extern "C" void kernel_launch(void* const* d_in, const int* in_sizes, int n_in,
                              void* d_out, int out_size) {
    const float* x    = (const float*)d_in[0];
    const int*   idx  = (const int*)  d_in[1];
    const float* w    = (const float*)d_in[2];
    const float* bias = (const float*)d_in[3];
    float*       out  = (float*)d_out;

    reset_kernel<<<1, 1>>>();
    mega_kernel<<<GRID_TOTAL, 256>>>(x, idx, w, bias, out);
}